// round 1
// baseline (speedup 1.0000x reference)
#include <cuda_runtime.h>

#define B_  1024
#define G_  2000
#define S_  32
#define H_  64
#define NCHUNK 18   // split-K chunks: 4 (gene/W0) + 8 (z1/W1) + 4 (z2/W2) + 2 (z3/W3)

// Scratch (static device globals — allocation-free per harness rules)
__device__ float g_gene[B_ * G_];            // 8 MB
__device__ float g_part[NCHUNK * B_ * H_];   // 4.7 MB

// ---------------- packed fp32x2 helpers (sm_103a full-rate FMA path) ----------
__device__ __forceinline__ unsigned long long dup2(float v) {
    unsigned long long r;
    asm("mov.b64 %0, {%1, %1};" : "=l"(r) : "f"(v));
    return r;
}
__device__ __forceinline__ void ffma2(unsigned long long& d,
                                      unsigned long long a, unsigned long long b) {
    asm("fma.rn.f32x2 %0, %1, %2, %0;" : "+l"(d) : "l"(a), "l"(b));
}
__device__ __forceinline__ float2 unpk(unsigned long long v) {
    float2 r;
    asm("mov.b64 {%0, %1}, %2;" : "=f"(r.x), "=f"(r.y) : "l"(v));
    return r;
}

// =============================================================================
// Kernel A: gene[b,g] = relu(dot(x[b, g*32:(g+1)*32], Wg[g,:]) + bg[g])
// One warp processes 4 genes per iteration: lane loads one float4 (512B/warp,
// fully coalesced), 8-lane tree reduction, lane 0 stores a float4 of results.
// x is streamed with .cs (no reuse); Wg (256 KB) stays L2-resident.
// =============================================================================
__global__ void __launch_bounds__(256) gene_kernel(const float* __restrict__ x,
                                                   const float* __restrict__ Wg,
                                                   const float* __restrict__ bg)
{
    const int b    = blockIdx.y;
    const int lane = threadIdx.x & 31;
    const int warp = threadIdx.x >> 5;
    const int nw   = (blockDim.x >> 5) * gridDim.x;
    const int w0   = blockIdx.x * (blockDim.x >> 5) + warp;
    const float* xrow = x + (size_t)b * (G_ * S_);

    for (int p = w0; p < G_ / 4; p += nw) {
        const float4 xv = __ldcs((const float4*)(xrow + p * 128 + lane * 4));
        const float4 wv = *(const float4*)(Wg + p * 128 + lane * 4);
        float d = xv.x * wv.x + xv.y * wv.y + xv.z * wv.z + xv.w * wv.w;
        d += __shfl_down_sync(0xffffffffu, d, 4);
        d += __shfl_down_sync(0xffffffffu, d, 2);
        d += __shfl_down_sync(0xffffffffu, d, 1);
        const float r0 = __shfl_sync(0xffffffffu, d, 0);
        const float r1 = __shfl_sync(0xffffffffu, d, 8);
        const float r2 = __shfl_sync(0xffffffffu, d, 16);
        const float r3 = __shfl_sync(0xffffffffu, d, 24);
        if (lane == 0) {
            const int g = p * 4;
            const float4 bv = *(const float4*)(bg + g);
            float4 o;
            o.x = fmaxf(r0 + bv.x, 0.0f);
            o.y = fmaxf(r1 + bv.y, 0.0f);
            o.z = fmaxf(r2 + bv.z, 0.0f);
            o.w = fmaxf(r3 + bv.w, 0.0f);
            *(float4*)(g_gene + (size_t)b * G_ + g) = o;
        }
    }
}

// =============================================================================
// Kernel B: split-K GEMM partials. Each block: 64 rows x 64 cols x (<=512) K,
// writing a deterministic partial to g_part[chunk]. Inner loop uses packed
// fma.rn.f32x2 (2 fp32 FMA / instr — full-rate on sm_103a vs rt=2 FFMA).
// Register double-buffering overlaps next gmem tile with compute.
// =============================================================================
struct TileRegs { float4 a0, a1, b0, b1; };

__device__ __forceinline__ void load_tile(TileRegs& r,
                                          const float* __restrict__ Ab,
                                          const float* __restrict__ Wb,
                                          int lda, int klen, int kk,
                                          int arow, int af4, int t)
{
    const int kg = kk + af4;
    #pragma unroll
    for (int i = 0; i < 2; i++) {
        const int row = arow + 32 * i;
        const float* ap = Ab + (size_t)row * lda;
        float4 v;
        if (kg + 3 < klen) {
            v = *(const float4*)(ap + kg);
        } else {
            v.x = (kg + 0 < klen) ? ap[kg + 0] : 0.0f;
            v.y = (kg + 1 < klen) ? ap[kg + 1] : 0.0f;
            v.z = (kg + 2 < klen) ? ap[kg + 2] : 0.0f;
            v.w = (kg + 3 < klen) ? ap[kg + 3] : 0.0f;
        }
        if (i == 0) r.a0 = v; else r.a1 = v;
    }
    #pragma unroll
    for (int i = 0; i < 2; i++) {
        const int q  = t + 256 * i;
        const int kr = kk + (q >> 4);
        float4 v = make_float4(0.f, 0.f, 0.f, 0.f);
        if (kr < klen) v = *(const float4*)(Wb + (size_t)kr * 64 + (q & 15) * 4);
        if (i == 0) r.b0 = v; else r.b1 = v;
    }
}

__global__ void __launch_bounds__(256) gemm_part_kernel(
    const float* __restrict__ z1, const float* __restrict__ z2,
    const float* __restrict__ z3,
    const float* __restrict__ W0, const float* __restrict__ W1,
    const float* __restrict__ W2, const float* __restrict__ W3)
{
    const int c = blockIdx.y;
    int m, k0, klen = 512;
    if      (c < 4)  { m = 0; k0 = c * 512;        if (c == 3) klen = G_ - 1536; }
    else if (c < 12) { m = 1; k0 = (c - 4)  * 512; }
    else if (c < 16) { m = 2; k0 = (c - 12) * 512; }
    else             { m = 3; k0 = (c - 16) * 512; }

    const float* A; const float* W; int lda;
    if      (m == 0) { A = g_gene; W = W0; lda = G_;   }
    else if (m == 1) { A = z1;     W = W1; lda = 4096; }
    else if (m == 2) { A = z2;     W = W2; lda = 2048; }
    else             { A = z3;     W = W3; lda = 1024; }

    const int row0 = blockIdx.x * 64;
    const float* Ab = A + (size_t)row0 * lda + k0;
    const float* Wb = W + (size_t)k0 * 64;

    __shared__ float As[32][66];   // [k][row], stride 66: conflict-light + 8B aligned pairs
    __shared__ float Bs[32 * 64];  // [k][col]

    const int t    = threadIdx.x;
    const int tx   = t & 15;
    const int ty   = t >> 4;
    const int arow = t >> 3;
    const int af4  = (t & 7) * 4;
    const int ksteps = (klen + 31) >> 5;

    unsigned long long acc[2][4];
    #pragma unroll
    for (int p = 0; p < 2; p++)
        #pragma unroll
        for (int q = 0; q < 4; q++) acc[p][q] = 0ull;

    TileRegs reg;
    load_tile(reg, Ab, Wb, lda, klen, 0, arow, af4, t);

    for (int ks = 0; ks < ksteps; ks++) {
        __syncthreads();
        // store staged tile
        As[af4 + 0][arow]      = reg.a0.x;
        As[af4 + 1][arow]      = reg.a0.y;
        As[af4 + 2][arow]      = reg.a0.z;
        As[af4 + 3][arow]      = reg.a0.w;
        As[af4 + 0][arow + 32] = reg.a1.x;
        As[af4 + 1][arow + 32] = reg.a1.y;
        As[af4 + 2][arow + 32] = reg.a1.z;
        As[af4 + 3][arow + 32] = reg.a1.w;
        *(float4*)(Bs + (size_t)t * 4)         = reg.b0;
        *(float4*)(Bs + (size_t)(t + 256) * 4) = reg.b1;
        __syncthreads();

        if (ks + 1 < ksteps)
            load_tile(reg, Ab, Wb, lda, klen, (ks + 1) * 32, arow, af4, t);

        #pragma unroll
        for (int k = 0; k < 32; k++) {
            const unsigned long long A0 = *(const unsigned long long*)&As[k][ty * 4];
            const unsigned long long A1 = *(const unsigned long long*)&As[k][ty * 4 + 2];
            const float4 bv = *(const float4*)(Bs + k * 64 + tx * 4);
            const unsigned long long Bq0 = dup2(bv.x);
            const unsigned long long Bq1 = dup2(bv.y);
            const unsigned long long Bq2 = dup2(bv.z);
            const unsigned long long Bq3 = dup2(bv.w);
            ffma2(acc[0][0], A0, Bq0); ffma2(acc[0][1], A0, Bq1);
            ffma2(acc[0][2], A0, Bq2); ffma2(acc[0][3], A0, Bq3);
            ffma2(acc[1][0], A1, Bq0); ffma2(acc[1][1], A1, Bq1);
            ffma2(acc[1][2], A1, Bq2); ffma2(acc[1][3], A1, Bq3);
        }
    }

    // epilogue: unpack row pairs, write partials (no atomics → deterministic)
    float* outp = g_part + ((size_t)c * B_ + row0 + ty * 4) * 64 + tx * 4;
    #pragma unroll
    for (int p = 0; p < 2; p++) {
        const float2 u0 = unpk(acc[p][0]);
        const float2 u1 = unpk(acc[p][1]);
        const float2 u2 = unpk(acc[p][2]);
        const float2 u3 = unpk(acc[p][3]);
        *(float4*)(outp + (size_t)(2 * p) * 64)     = make_float4(u0.x, u1.x, u2.x, u3.x);
        *(float4*)(outp + (size_t)(2 * p + 1) * 64) = make_float4(u0.y, u1.y, u2.y, u3.y);
    }
}

// =============================================================================
// Kernel C: reduce split-K partials, biases/relu/weighted fusion, then the
// 64->64->64->1 MLP. 4 batch rows per 256-thread block; fW1/fW2 in smem.
// =============================================================================
__global__ void __launch_bounds__(256) finish_kernel(
    const float* __restrict__ b0, const float* __restrict__ b1,
    const float* __restrict__ b2, const float* __restrict__ b3,
    const float* __restrict__ w1, const float* __restrict__ w2,
    const float* __restrict__ w3,
    const float* __restrict__ fW1, const float* __restrict__ fb1,
    const float* __restrict__ fW2, const float* __restrict__ fb2,
    const float* __restrict__ fW3, const float* __restrict__ fb3,
    float* __restrict__ out)
{
    __shared__ float sW1[64 * 64];
    __shared__ float sW2[64 * 64];
    __shared__ float sbuf[4][64];
    __shared__ float sred[8];

    const int t = threadIdx.x;
    const int h = t & 63;
    const int r = t >> 6;
    for (int i = t; i < 64 * 64; i += 256) { sW1[i] = fW1[i]; sW2[i] = fW2[i]; }

    const int b = blockIdx.x * 4 + r;

    float a0 = 0.f, a1 = 0.f, a2 = 0.f, a3 = 0.f;
    #pragma unroll
    for (int cc = 0;  cc < 4;  cc++) a0 += g_part[((size_t)cc * B_ + b) * 64 + h];
    #pragma unroll
    for (int cc = 4;  cc < 12; cc++) a1 += g_part[((size_t)cc * B_ + b) * 64 + h];
    #pragma unroll
    for (int cc = 12; cc < 16; cc++) a2 += g_part[((size_t)cc * B_ + b) * 64 + h];
    #pragma unroll
    for (int cc = 16; cc < 18; cc++) a3 += g_part[((size_t)cc * B_ + b) * 64 + h];

    float d = fmaxf(a0 + b0[h], 0.f);
    d += fmaxf(a1 + b1[h], 0.f) * w1[h];
    d += fmaxf(a2 + b2[h], 0.f) * w2[h];
    d += fmaxf(a3 + b3[h], 0.f) * w3[h];

    __syncthreads();            // weights staged
    sbuf[r][h] = d;
    __syncthreads();
    float acc = fb1[h];
    #pragma unroll
    for (int k = 0; k < 64; k++) acc = fmaf(sbuf[r][k], sW1[k * 64 + h], acc);
    const float hv = fmaxf(acc, 0.f);
    __syncthreads();
    sbuf[r][h] = hv;
    __syncthreads();
    acc = fb2[h];
    #pragma unroll
    for (int k = 0; k < 64; k++) acc = fmaf(sbuf[r][k], sW2[k * 64 + h], acc);
    const float h2 = fmaxf(acc, 0.f);

    float val = h2 * fW3[h];
    #pragma unroll
    for (int off = 16; off; off >>= 1) val += __shfl_down_sync(0xffffffffu, val, off);
    if ((t & 31) == 0) sred[t >> 5] = val;
    __syncthreads();
    if (h == 0) out[b] = sred[2 * r] + sred[2 * r + 1] + fb3[0];
}

// =============================================================================
// Launcher (graph-capturable: 3 kernel launches, no sync, no alloc)
// Input order per metadata: x, z1, z2, z3, Wg, bg, W0, b0, W1, b1, W2, b2,
// W3, b3, w1, w2, w3, fW1, fb1, fW2, fb2, fW3, fb3
// =============================================================================
extern "C" void kernel_launch(void* const* d_in, const int* in_sizes, int n_in,
                              void* d_out, int out_size)
{
    const float* x   = (const float*)d_in[0];
    const float* z1  = (const float*)d_in[1];
    const float* z2  = (const float*)d_in[2];
    const float* z3  = (const float*)d_in[3];
    const float* Wg  = (const float*)d_in[4];
    const float* bg  = (const float*)d_in[5];
    const float* W0  = (const float*)d_in[6];
    const float* b0  = (const float*)d_in[7];
    const float* W1  = (const float*)d_in[8];
    const float* b1  = (const float*)d_in[9];
    const float* W2  = (const float*)d_in[10];
    const float* b2  = (const float*)d_in[11];
    const float* W3  = (const float*)d_in[12];
    const float* b3  = (const float*)d_in[13];
    const float* w1  = (const float*)d_in[14];
    const float* w2  = (const float*)d_in[15];
    const float* w3  = (const float*)d_in[16];
    const float* fW1 = (const float*)d_in[17];
    const float* fb1 = (const float*)d_in[18];
    const float* fW2 = (const float*)d_in[19];
    const float* fb2 = (const float*)d_in[20];
    const float* fW3 = (const float*)d_in[21];
    const float* fb3 = (const float*)d_in[22];
    float* out = (float*)d_out;

    gene_kernel<<<dim3(4, B_), 256>>>(x, Wg, bg);
    gemm_part_kernel<<<dim3(B_ / 64, NCHUNK), 256>>>(z1, z2, z3, W0, W1, W2, W3);
    finish_kernel<<<B_ / 4, 256>>>(b0, b1, b2, b3, w1, w2, w3,
                                   fW1, fb1, fW2, fb2, fW3, fb3, out);
}

// round 2
// speedup vs baseline: 1.0162x; 1.0162x over previous
#include <cuda_runtime.h>

#define B_  1024
#define G_  2000
#define S_  32
#define H_  64
#define NCHUNK 18        // 4 (gene/W0) + 8 (z1/W1) + 4 (z2/W2) + 2 (z3/W3)
#define NZBLK  224       // 14 z-chunks * 16 row tiles
#define GENEBLK 960      // gene-streaming blocks in the fused kernel
#define GENE_ITEMS (B_ * (G_ / 4))   // 512000 warp-items, 4 genes each

// Scratch (static device globals — allocation-free per harness rules)
__device__ float g_gene[B_ * G_];            // 8 MB
__device__ float g_part[NCHUNK * B_ * H_];   // 4.7 MB

// ---------------- packed fp32x2 helpers (sm_103a full-rate FMA path) ----------
__device__ __forceinline__ unsigned long long dup2(float v) {
    unsigned long long r;
    asm("mov.b64 %0, {%1, %1};" : "=l"(r) : "f"(v));
    return r;
}
__device__ __forceinline__ void ffma2(unsigned long long& d,
                                      unsigned long long a, unsigned long long b) {
    asm("fma.rn.f32x2 %0, %1, %2, %0;" : "+l"(d) : "l"(a), "l"(b));
}
__device__ __forceinline__ float2 unpk(unsigned long long v) {
    float2 r;
    asm("mov.b64 {%0, %1}, %2;" : "=f"(r.x), "=f"(r.y) : "l"(v));
    return r;
}

// =============================================================================
// Shared GEMM body: one 64x64 output tile over a <=512-wide K chunk, writing a
// deterministic partial to g_part[c]. Inner loop on packed fma.rn.f32x2.
// =============================================================================
struct TileRegs { float4 a0, a1, b0, b1; };

__device__ __forceinline__ void load_tile(TileRegs& r,
                                          const float* __restrict__ Ab,
                                          const float* __restrict__ Wb,
                                          int lda, int klen, int kk,
                                          int arow, int af4, int t)
{
    const int kg = kk + af4;
    #pragma unroll
    for (int i = 0; i < 2; i++) {
        const int row = arow + 32 * i;
        const float* ap = Ab + (size_t)row * lda;
        float4 v;
        if (kg + 3 < klen) {
            v = *(const float4*)(ap + kg);
        } else {
            v.x = (kg + 0 < klen) ? ap[kg + 0] : 0.0f;
            v.y = (kg + 1 < klen) ? ap[kg + 1] : 0.0f;
            v.z = (kg + 2 < klen) ? ap[kg + 2] : 0.0f;
            v.w = (kg + 3 < klen) ? ap[kg + 3] : 0.0f;
        }
        if (i == 0) r.a0 = v; else r.a1 = v;
    }
    #pragma unroll
    for (int i = 0; i < 2; i++) {
        const int q  = t + 256 * i;
        const int kr = kk + (q >> 4);
        float4 v = make_float4(0.f, 0.f, 0.f, 0.f);
        if (kr < klen) v = *(const float4*)(Wb + (size_t)kr * 64 + (q & 15) * 4);
        if (i == 0) r.b0 = v; else r.b1 = v;
    }
}

__device__ __forceinline__ void gemm_body(const float* __restrict__ A,
                                          const float* __restrict__ W,
                                          int lda, int k0, int klen,
                                          int c, int row0)
{
    __shared__ float As[32][66];
    __shared__ float Bs[32 * 64];

    const float* Ab = A + (size_t)row0 * lda + k0;
    const float* Wb = W + (size_t)k0 * 64;

    const int t    = threadIdx.x;
    const int tx   = t & 15;
    const int ty   = t >> 4;
    const int arow = t >> 3;
    const int af4  = (t & 7) * 4;
    const int ksteps = (klen + 31) >> 5;

    unsigned long long acc[2][4];
    #pragma unroll
    for (int p = 0; p < 2; p++)
        #pragma unroll
        for (int q = 0; q < 4; q++) acc[p][q] = 0ull;

    TileRegs reg;
    load_tile(reg, Ab, Wb, lda, klen, 0, arow, af4, t);

    for (int ks = 0; ks < ksteps; ks++) {
        __syncthreads();
        As[af4 + 0][arow]      = reg.a0.x;
        As[af4 + 1][arow]      = reg.a0.y;
        As[af4 + 2][arow]      = reg.a0.z;
        As[af4 + 3][arow]      = reg.a0.w;
        As[af4 + 0][arow + 32] = reg.a1.x;
        As[af4 + 1][arow + 32] = reg.a1.y;
        As[af4 + 2][arow + 32] = reg.a1.z;
        As[af4 + 3][arow + 32] = reg.a1.w;
        *(float4*)(Bs + (size_t)t * 4)         = reg.b0;
        *(float4*)(Bs + (size_t)(t + 256) * 4) = reg.b1;
        __syncthreads();

        if (ks + 1 < ksteps)
            load_tile(reg, Ab, Wb, lda, klen, (ks + 1) * 32, arow, af4, t);

        #pragma unroll
        for (int k = 0; k < 32; k++) {
            const unsigned long long A0 = *(const unsigned long long*)&As[k][ty * 4];
            const unsigned long long A1 = *(const unsigned long long*)&As[k][ty * 4 + 2];
            const float4 bv = *(const float4*)(Bs + k * 64 + tx * 4);
            const unsigned long long Bq0 = dup2(bv.x);
            const unsigned long long Bq1 = dup2(bv.y);
            const unsigned long long Bq2 = dup2(bv.z);
            const unsigned long long Bq3 = dup2(bv.w);
            ffma2(acc[0][0], A0, Bq0); ffma2(acc[0][1], A0, Bq1);
            ffma2(acc[0][2], A0, Bq2); ffma2(acc[0][3], A0, Bq3);
            ffma2(acc[1][0], A1, Bq0); ffma2(acc[1][1], A1, Bq1);
            ffma2(acc[1][2], A1, Bq2); ffma2(acc[1][3], A1, Bq3);
        }
    }

    float* outp = g_part + ((size_t)c * B_ + row0 + ty * 4) * 64 + tx * 4;
    #pragma unroll
    for (int p = 0; p < 2; p++) {
        const float2 u0 = unpk(acc[p][0]);
        const float2 u1 = unpk(acc[p][1]);
        const float2 u2 = unpk(acc[p][2]);
        const float2 u3 = unpk(acc[p][3]);
        *(float4*)(outp + (size_t)(2 * p) * 64)     = make_float4(u0.x, u1.x, u2.x, u3.x);
        *(float4*)(outp + (size_t)(2 * p + 1) * 64) = make_float4(u0.y, u1.y, u2.y, u3.y);
    }
}

// =============================================================================
// Fused kernel: blocks [0, NZBLK) run the 14 z-GEMM chunks (compute-bound),
// blocks [NZBLK, NZBLK+GENEBLK) stream the gene stage (memory-bound).
// The two populations are independent and co-resident — GEMM FMA work hides
// under the gene stage's DRAM streaming.
// =============================================================================
__global__ void __launch_bounds__(256) fused_kernel(
    const float* __restrict__ x,
    const float* __restrict__ z1, const float* __restrict__ z2,
    const float* __restrict__ z3,
    const float* __restrict__ Wg, const float* __restrict__ bg,
    const float* __restrict__ W1, const float* __restrict__ W2,
    const float* __restrict__ W3)
{
    const int bid = blockIdx.x;
    if (bid < NZBLK) {
        // ---- z-GEMM population ----
        const int c    = (bid >> 4) + 4;      // chunks 4..17
        const int row0 = (bid & 15) * 64;
        const float* A; const float* W; int lda, k0;
        if (c < 12)      { A = z1; W = W1; lda = 4096; k0 = (c - 4)  * 512; }
        else if (c < 16) { A = z2; W = W2; lda = 2048; k0 = (c - 12) * 512; }
        else             { A = z3; W = W3; lda = 1024; k0 = (c - 16) * 512; }
        gemm_body(A, W, lda, k0, 512, c, row0);
        return;
    }

    // ---- gene population: 4 genes per warp-item, unrolled x4 ----
    const int lane = threadIdx.x & 31;
    const int w    = (bid - NZBLK) * 8 + (threadIdx.x >> 5);
    const int nW   = GENEBLK * 8;

    for (int it = w; it < GENE_ITEMS; it += nW * 4) {
        float d[4];
        #pragma unroll
        for (int j = 0; j < 4; j++) {
            const int item = it + j * nW;
            d[j] = 0.0f;
            if (item < GENE_ITEMS) {
                const int b = item / 500;          // G_/4 = 500 items per row
                const int p = item - b * 500;
                const size_t off = (size_t)b * (G_ * S_) + (size_t)p * 128 + lane * 4;
                const float4 xv = __ldcs((const float4*)(x + off));
                const float4 wv = __ldg((const float4*)(Wg + (size_t)p * 128 + lane * 4));
                d[j] = xv.x * wv.x + xv.y * wv.y + xv.z * wv.z + xv.w * wv.w;
            }
        }
        #pragma unroll
        for (int j = 0; j < 4; j++) {
            d[j] += __shfl_down_sync(0xffffffffu, d[j], 4);
            d[j] += __shfl_down_sync(0xffffffffu, d[j], 2);
            d[j] += __shfl_down_sync(0xffffffffu, d[j], 1);
        }
        if ((lane & 7) == 0) {
            #pragma unroll
            for (int j = 0; j < 4; j++) {
                const int item = it + j * nW;
                if (item < GENE_ITEMS) {
                    const int b = item / 500;
                    const int p = item - b * 500;
                    const int g = p * 4 + (lane >> 3);
                    g_gene[(size_t)b * G_ + g] = fmaxf(d[j] + __ldg(bg + g), 0.0f);
                }
            }
        }
    }
}

// =============================================================================
// Gene-GEMM kernel: chunks 0..3 (depend on g_gene).
// =============================================================================
__global__ void __launch_bounds__(256) gene_gemm_kernel(const float* __restrict__ W0)
{
    const int c    = blockIdx.y;                  // 0..3
    const int row0 = blockIdx.x * 64;
    const int k0   = c * 512;
    const int klen = (c == 3) ? (G_ - 1536) : 512;
    gemm_body(g_gene, W0, G_, k0, klen, c, row0);
}

// =============================================================================
// Finish kernel: reduce split-K partials, fusion, final 64->64->64->1 MLP.
// =============================================================================
__global__ void __launch_bounds__(256) finish_kernel(
    const float* __restrict__ b0, const float* __restrict__ b1,
    const float* __restrict__ b2, const float* __restrict__ b3,
    const float* __restrict__ w1, const float* __restrict__ w2,
    const float* __restrict__ w3,
    const float* __restrict__ fW1, const float* __restrict__ fb1,
    const float* __restrict__ fW2, const float* __restrict__ fb2,
    const float* __restrict__ fW3, const float* __restrict__ fb3,
    float* __restrict__ out)
{
    __shared__ float sW1[64 * 64];
    __shared__ float sW2[64 * 64];
    __shared__ float sbuf[4][64];
    __shared__ float sred[8];

    const int t = threadIdx.x;
    const int h = t & 63;
    const int r = t >> 6;
    for (int i = t; i < 64 * 64; i += 256) { sW1[i] = fW1[i]; sW2[i] = fW2[i]; }

    const int b = blockIdx.x * 4 + r;

    float a0 = 0.f, a1 = 0.f, a2 = 0.f, a3 = 0.f;
    #pragma unroll
    for (int cc = 0;  cc < 4;  cc++) a0 += g_part[((size_t)cc * B_ + b) * 64 + h];
    #pragma unroll
    for (int cc = 4;  cc < 12; cc++) a1 += g_part[((size_t)cc * B_ + b) * 64 + h];
    #pragma unroll
    for (int cc = 12; cc < 16; cc++) a2 += g_part[((size_t)cc * B_ + b) * 64 + h];
    #pragma unroll
    for (int cc = 16; cc < 18; cc++) a3 += g_part[((size_t)cc * B_ + b) * 64 + h];

    float d = fmaxf(a0 + b0[h], 0.f);
    d += fmaxf(a1 + b1[h], 0.f) * w1[h];
    d += fmaxf(a2 + b2[h], 0.f) * w2[h];
    d += fmaxf(a3 + b3[h], 0.f) * w3[h];

    __syncthreads();
    sbuf[r][h] = d;
    __syncthreads();
    float acc = fb1[h];
    #pragma unroll
    for (int k = 0; k < 64; k++) acc = fmaf(sbuf[r][k], sW1[k * 64 + h], acc);
    const float hv = fmaxf(acc, 0.f);
    __syncthreads();
    sbuf[r][h] = hv;
    __syncthreads();
    acc = fb2[h];
    #pragma unroll
    for (int k = 0; k < 64; k++) acc = fmaf(sbuf[r][k], sW2[k * 64 + h], acc);
    const float h2 = fmaxf(acc, 0.f);

    float val = h2 * fW3[h];
    #pragma unroll
    for (int off = 16; off; off >>= 1) val += __shfl_down_sync(0xffffffffu, val, off);
    if ((t & 31) == 0) sred[t >> 5] = val;
    __syncthreads();
    if (h == 0) out[b] = sred[2 * r] + sred[2 * r + 1] + fb3[0];
}

// =============================================================================
// Launcher (graph-capturable: 3 kernel launches, no sync, no alloc)
// =============================================================================
extern "C" void kernel_launch(void* const* d_in, const int* in_sizes, int n_in,
                              void* d_out, int out_size)
{
    const float* x   = (const float*)d_in[0];
    const float* z1  = (const float*)d_in[1];
    const float* z2  = (const float*)d_in[2];
    const float* z3  = (const float*)d_in[3];
    const float* Wg  = (const float*)d_in[4];
    const float* bg  = (const float*)d_in[5];
    const float* W0  = (const float*)d_in[6];
    const float* b0  = (const float*)d_in[7];
    const float* W1  = (const float*)d_in[8];
    const float* b1  = (const float*)d_in[9];
    const float* W2  = (const float*)d_in[10];
    const float* b2  = (const float*)d_in[11];
    const float* W3  = (const float*)d_in[12];
    const float* b3  = (const float*)d_in[13];
    const float* w1  = (const float*)d_in[14];
    const float* w2  = (const float*)d_in[15];
    const float* w3  = (const float*)d_in[16];
    const float* fW1 = (const float*)d_in[17];
    const float* fb1 = (const float*)d_in[18];
    const float* fW2 = (const float*)d_in[19];
    const float* fb2 = (const float*)d_in[20];
    const float* fW3 = (const float*)d_in[21];
    const float* fb3 = (const float*)d_in[22];
    float* out = (float*)d_out;

    fused_kernel<<<NZBLK + GENEBLK, 256>>>(x, z1, z2, z3, Wg, bg, W1, W2, W3);
    gene_gemm_kernel<<<dim3(B_ / 64, 4), 256>>>(W0);
    finish_kernel<<<B_ / 4, 256>>>(b0, b1, b2, b3, w1, w2, w3,
                                   fW1, fb1, fW2, fb2, fW3, fb3, out);
}

// round 3
// speedup vs baseline: 1.0674x; 1.0504x over previous
#include <cuda_runtime.h>

#define B_  1024
#define G_  2000
#define S_  32
#define H_  64
#define NCHUNK 24        // 10 (gene/W0, K=200) + 8 (z1) + 4 (z2) + 2 (z3)
#define NZBLK  224       // 14 z-chunks * 16 row tiles
#define GENEBLK 516      // 224 + 516 = 740 = 148 SMs * 5 blocks
#define GENE_ITEMS (B_ * (G_ / 4))   // 512000 warp-items, 4 genes each

// Scratch (static device globals — allocation-free per harness rules)
__device__ float g_gene[B_ * G_];            // 8 MB
__device__ float g_part[NCHUNK * B_ * H_];   // 6.3 MB

// ---------------- packed fp32x2 helpers (sm_103a full-rate FMA path) ----------
__device__ __forceinline__ unsigned long long dup2(float v) {
    unsigned long long r;
    asm("mov.b64 %0, {%1, %1};" : "=l"(r) : "f"(v));
    return r;
}
__device__ __forceinline__ void ffma2(unsigned long long& d,
                                      unsigned long long a, unsigned long long b) {
    asm("fma.rn.f32x2 %0, %1, %2, %0;" : "+l"(d) : "l"(a), "l"(b));
}
__device__ __forceinline__ float2 unpk(unsigned long long v) {
    float2 r;
    asm("mov.b64 {%0, %1}, %2;" : "=f"(r.x), "=f"(r.y) : "l"(v));
    return r;
}

// =============================================================================
// GEMM body (single-buffered smem staging, ~low reg count): one 64x64 output
// tile over a <=512-wide K chunk; deterministic partial into g_part[c].
// =============================================================================
template <bool STREAM_A>
__device__ __forceinline__ void gemm_body(const float* __restrict__ A,
                                          const float* __restrict__ W,
                                          int lda, int k0, int klen,
                                          int c, int row0)
{
    __shared__ float As[32][66];
    __shared__ float Bs[32 * 64];

    const float* Ab = A + (size_t)row0 * lda + k0;
    const float* Wb = W + (size_t)k0 * 64;

    const int t    = threadIdx.x;
    const int tx   = t & 15;
    const int ty   = t >> 4;
    const int arow = t >> 3;
    const int af4  = (t & 7) * 4;
    const int ksteps = (klen + 31) >> 5;

    unsigned long long acc[2][4];
    #pragma unroll
    for (int p = 0; p < 2; p++)
        #pragma unroll
        for (int q = 0; q < 4; q++) acc[p][q] = 0ull;

    for (int ks = 0; ks < ksteps; ks++) {
        const int kk = ks * 32;
        const int kg = kk + af4;

        // ---- load tile (scheduled into previous iteration's compute) ----
        float4 av[2];
        #pragma unroll
        for (int i = 0; i < 2; i++) {
            const float* ap = Ab + (size_t)(arow + 32 * i) * lda;
            float4 v;
            if (kg + 3 < klen) {
                v = STREAM_A ? __ldcs((const float4*)(ap + kg))
                             : *(const float4*)(ap + kg);
            } else {
                v.x = (kg + 0 < klen) ? ap[kg + 0] : 0.0f;
                v.y = (kg + 1 < klen) ? ap[kg + 1] : 0.0f;
                v.z = (kg + 2 < klen) ? ap[kg + 2] : 0.0f;
                v.w = (kg + 3 < klen) ? ap[kg + 3] : 0.0f;
            }
            av[i] = v;
        }
        float4 bv2[2];
        #pragma unroll
        for (int i = 0; i < 2; i++) {
            const int q  = t + 256 * i;
            const int kr = kk + (q >> 4);
            float4 v = make_float4(0.f, 0.f, 0.f, 0.f);
            if (kr < klen) v = *(const float4*)(Wb + (size_t)kr * 64 + (q & 15) * 4);
            bv2[i] = v;
        }

        __syncthreads();   // previous compute done
        #pragma unroll
        for (int i = 0; i < 2; i++) {
            As[af4 + 0][arow + 32 * i] = av[i].x;
            As[af4 + 1][arow + 32 * i] = av[i].y;
            As[af4 + 2][arow + 32 * i] = av[i].z;
            As[af4 + 3][arow + 32 * i] = av[i].w;
        }
        *(float4*)(Bs + (size_t)t * 4)         = bv2[0];
        *(float4*)(Bs + (size_t)(t + 256) * 4) = bv2[1];
        __syncthreads();

        #pragma unroll
        for (int k = 0; k < 32; k++) {
            const unsigned long long A0 = *(const unsigned long long*)&As[k][ty * 4];
            const unsigned long long A1 = *(const unsigned long long*)&As[k][ty * 4 + 2];
            const float4 bv = *(const float4*)(Bs + k * 64 + tx * 4);
            const unsigned long long Bq0 = dup2(bv.x);
            const unsigned long long Bq1 = dup2(bv.y);
            const unsigned long long Bq2 = dup2(bv.z);
            const unsigned long long Bq3 = dup2(bv.w);
            ffma2(acc[0][0], A0, Bq0); ffma2(acc[1][0], A1, Bq0);
            ffma2(acc[0][1], A0, Bq1); ffma2(acc[1][1], A1, Bq1);
            ffma2(acc[0][2], A0, Bq2); ffma2(acc[1][2], A1, Bq2);
            ffma2(acc[0][3], A0, Bq3); ffma2(acc[1][3], A1, Bq3);
        }
    }

    float* outp = g_part + ((size_t)c * B_ + row0 + ty * 4) * 64 + tx * 4;
    #pragma unroll
    for (int p = 0; p < 2; p++) {
        const float2 u0 = unpk(acc[p][0]);
        const float2 u1 = unpk(acc[p][1]);
        const float2 u2 = unpk(acc[p][2]);
        const float2 u3 = unpk(acc[p][3]);
        *(float4*)(outp + (size_t)(2 * p) * 64)     = make_float4(u0.x, u1.x, u2.x, u3.x);
        *(float4*)(outp + (size_t)(2 * p + 1) * 64) = make_float4(u0.y, u1.y, u2.y, u3.y);
    }
}

// =============================================================================
// Fused kernel: blocks [0, NZBLK) run the 14 z-GEMM chunks, blocks
// [NZBLK, 740) stream the gene stage. One wave at 5 blocks/SM.
// =============================================================================
__global__ void __launch_bounds__(256, 5) fused_kernel(
    const float* __restrict__ x,
    const float* __restrict__ z1, const float* __restrict__ z2,
    const float* __restrict__ z3,
    const float* __restrict__ Wg, const float* __restrict__ bg,
    const float* __restrict__ W1, const float* __restrict__ W2,
    const float* __restrict__ W3)
{
    const int bid = blockIdx.x;
    if (bid < NZBLK) {
        const int zc   = bid >> 4;            // 0..13
        const int row0 = (bid & 15) * 64;
        const float* A; const float* W; int lda, k0;
        if (zc < 8)       { A = z1; W = W1; lda = 4096; k0 = zc * 512; }
        else if (zc < 12) { A = z2; W = W2; lda = 2048; k0 = (zc - 8)  * 512; }
        else              { A = z3; W = W3; lda = 1024; k0 = (zc - 12) * 512; }
        gemm_body<true>(A, W, lda, k0, 512, 10 + zc, row0);
        return;
    }

    // ---- gene population: 4 genes per warp-item, unrolled x4 ----
    const int lane = threadIdx.x & 31;
    const int w    = (bid - NZBLK) * 8 + (threadIdx.x >> 5);
    const int nW   = GENEBLK * 8;

    for (int it = w; it < GENE_ITEMS; it += nW * 4) {
        float d[4];
        #pragma unroll
        for (int j = 0; j < 4; j++) {
            const int item = it + j * nW;
            d[j] = 0.0f;
            if (item < GENE_ITEMS) {
                const int b = item / 500;          // G_/4 = 500 items per row
                const int p = item - b * 500;
                const size_t off = (size_t)b * (G_ * S_) + (size_t)p * 128 + lane * 4;
                const float4 xv = __ldcs((const float4*)(x + off));
                const float4 wv = __ldg((const float4*)(Wg + (size_t)p * 128 + lane * 4));
                d[j] = xv.x * wv.x + xv.y * wv.y + xv.z * wv.z + xv.w * wv.w;
            }
        }
        #pragma unroll
        for (int j = 0; j < 4; j++) {
            d[j] += __shfl_down_sync(0xffffffffu, d[j], 4);
            d[j] += __shfl_down_sync(0xffffffffu, d[j], 2);
            d[j] += __shfl_down_sync(0xffffffffu, d[j], 1);
        }
        if ((lane & 7) == 0) {
            #pragma unroll
            for (int j = 0; j < 4; j++) {
                const int item = it + j * nW;
                if (item < GENE_ITEMS) {
                    const int b = item / 500;
                    const int p = item - b * 500;
                    const int g = p * 4 + (lane >> 3);
                    g_gene[(size_t)b * G_ + g] = fmaxf(d[j] + __ldg(bg + g), 0.0f);
                }
            }
        }
    }
}

// =============================================================================
// Gene-GEMM kernel: chunks 0..9 (K=200 each), 160 blocks = ~1 full wave.
// =============================================================================
__global__ void __launch_bounds__(256, 5) gene_gemm_kernel(const float* __restrict__ W0)
{
    const int c    = blockIdx.y;                  // 0..9
    const int row0 = blockIdx.x * 64;
    gemm_body<false>(g_gene, W0, G_, c * 200, 200, c, row0);
}

// =============================================================================
// Finish kernel: reduce split-K partials, fusion, final 64->64->64->1 MLP.
// =============================================================================
__global__ void __launch_bounds__(256) finish_kernel(
    const float* __restrict__ b0, const float* __restrict__ b1,
    const float* __restrict__ b2, const float* __restrict__ b3,
    const float* __restrict__ w1, const float* __restrict__ w2,
    const float* __restrict__ w3,
    const float* __restrict__ fW1, const float* __restrict__ fb1,
    const float* __restrict__ fW2, const float* __restrict__ fb2,
    const float* __restrict__ fW3, const float* __restrict__ fb3,
    float* __restrict__ out)
{
    __shared__ float sW1[64 * 64];
    __shared__ float sW2[64 * 64];
    __shared__ float sbuf[4][64];
    __shared__ float sred[8];

    const int t = threadIdx.x;
    const int h = t & 63;
    const int r = t >> 6;
    for (int i = t; i < 64 * 64; i += 256) { sW1[i] = fW1[i]; sW2[i] = fW2[i]; }

    const int b = blockIdx.x * 4 + r;

    float a0 = 0.f, a1 = 0.f, a2 = 0.f, a3 = 0.f;
    #pragma unroll
    for (int cc = 0;  cc < 10; cc++) a0 += g_part[((size_t)cc * B_ + b) * 64 + h];
    #pragma unroll
    for (int cc = 10; cc < 18; cc++) a1 += g_part[((size_t)cc * B_ + b) * 64 + h];
    #pragma unroll
    for (int cc = 18; cc < 22; cc++) a2 += g_part[((size_t)cc * B_ + b) * 64 + h];
    #pragma unroll
    for (int cc = 22; cc < 24; cc++) a3 += g_part[((size_t)cc * B_ + b) * 64 + h];

    float d = fmaxf(a0 + b0[h], 0.f);
    d += fmaxf(a1 + b1[h], 0.f) * w1[h];
    d += fmaxf(a2 + b2[h], 0.f) * w2[h];
    d += fmaxf(a3 + b3[h], 0.f) * w3[h];

    __syncthreads();
    sbuf[r][h] = d;
    __syncthreads();
    float acc = fb1[h];
    #pragma unroll
    for (int k = 0; k < 64; k++) acc = fmaf(sbuf[r][k], sW1[k * 64 + h], acc);
    const float hv = fmaxf(acc, 0.f);
    __syncthreads();
    sbuf[r][h] = hv;
    __syncthreads();
    acc = fb2[h];
    #pragma unroll
    for (int k = 0; k < 64; k++) acc = fmaf(sbuf[r][k], sW2[k * 64 + h], acc);
    const float h2 = fmaxf(acc, 0.f);

    float val = h2 * fW3[h];
    #pragma unroll
    for (int off = 16; off; off >>= 1) val += __shfl_down_sync(0xffffffffu, val, off);
    if ((t & 31) == 0) sred[t >> 5] = val;
    __syncthreads();
    if (h == 0) out[b] = sred[2 * r] + sred[2 * r + 1] + fb3[0];
}

// =============================================================================
// Launcher (graph-capturable: 3 kernel launches, no sync, no alloc)
// =============================================================================
extern "C" void kernel_launch(void* const* d_in, const int* in_sizes, int n_in,
                              void* d_out, int out_size)
{
    const float* x   = (const float*)d_in[0];
    const float* z1  = (const float*)d_in[1];
    const float* z2  = (const float*)d_in[2];
    const float* z3  = (const float*)d_in[3];
    const float* Wg  = (const float*)d_in[4];
    const float* bg  = (const float*)d_in[5];
    const float* W0  = (const float*)d_in[6];
    const float* b0  = (const float*)d_in[7];
    const float* W1  = (const float*)d_in[8];
    const float* b1  = (const float*)d_in[9];
    const float* W2  = (const float*)d_in[10];
    const float* b2  = (const float*)d_in[11];
    const float* W3  = (const float*)d_in[12];
    const float* b3  = (const float*)d_in[13];
    const float* w1  = (const float*)d_in[14];
    const float* w2  = (const float*)d_in[15];
    const float* w3  = (const float*)d_in[16];
    const float* fW1 = (const float*)d_in[17];
    const float* fb1 = (const float*)d_in[18];
    const float* fW2 = (const float*)d_in[19];
    const float* fb2 = (const float*)d_in[20];
    const float* fW3 = (const float*)d_in[21];
    const float* fb3 = (const float*)d_in[22];
    float* out = (float*)d_out;

    fused_kernel<<<NZBLK + GENEBLK, 256>>>(x, z1, z2, z3, Wg, bg, W1, W2, W3);
    gene_gemm_kernel<<<dim3(B_ / 64, 10), 256>>>(W0);
    finish_kernel<<<B_ / 4, 256>>>(b0, b1, b2, b3, w1, w2, w3,
                                   fW1, fb1, fW2, fb2, fW3, fb3, out);
}

// round 4
// speedup vs baseline: 1.1125x; 1.0422x over previous
#include <cuda_runtime.h>

#define B_  1024
#define G_  2000
#define S_  32
#define H_  64
#define NCHUNK 24        // 10 (gene/W0, K=200) + 8 (z1) + 4 (z2) + 2 (z3)
#define NZBLK  224       // 14 z-chunks * 16 row tiles
#define GENEBLK 250      // 2000 gene warp-tasks / 8 warps
#define ROWSTRIDE (G_ * S_)   // 64000 floats per x row

// Scratch (static device globals — allocation-free per harness rules)
__device__ float g_gene[B_ * G_];            // 8 MB
__device__ float g_part[NCHUNK * B_ * H_];   // 6.3 MB

// ---------------- packed fp32x2 helpers (sm_103a full-rate FMA path) ----------
__device__ __forceinline__ unsigned long long dup2(float v) {
    unsigned long long r;
    asm("mov.b64 %0, {%1, %1};" : "=l"(r) : "f"(v));
    return r;
}
__device__ __forceinline__ void ffma2(unsigned long long& d,
                                      unsigned long long a, unsigned long long b) {
    asm("fma.rn.f32x2 %0, %1, %2, %0;" : "+l"(d) : "l"(a), "l"(b));
}
__device__ __forceinline__ float2 unpk(unsigned long long v) {
    float2 r;
    asm("mov.b64 {%0, %1}, %2;" : "=f"(r.x), "=f"(r.y) : "l"(v));
    return r;
}

// =============================================================================
// GEMM body (single-buffered smem staging): one 64x64 output tile over a
// <=512-wide K chunk; deterministic partial into g_part[c].
// =============================================================================
template <bool STREAM_A>
__device__ __forceinline__ void gemm_body(const float* __restrict__ A,
                                          const float* __restrict__ W,
                                          int lda, int k0, int klen,
                                          int c, int row0)
{
    __shared__ float As[32][66];
    __shared__ float Bs[32 * 64];

    const float* Ab = A + (size_t)row0 * lda + k0;
    const float* Wb = W + (size_t)k0 * 64;

    const int t    = threadIdx.x;
    const int tx   = t & 15;
    const int ty   = t >> 4;
    const int arow = t >> 3;
    const int af4  = (t & 7) * 4;
    const int ksteps = (klen + 31) >> 5;

    unsigned long long acc[2][4];
    #pragma unroll
    for (int p = 0; p < 2; p++)
        #pragma unroll
        for (int q = 0; q < 4; q++) acc[p][q] = 0ull;

    for (int ks = 0; ks < ksteps; ks++) {
        const int kk = ks * 32;
        const int kg = kk + af4;

        float4 av[2];
        #pragma unroll
        for (int i = 0; i < 2; i++) {
            const float* ap = Ab + (size_t)(arow + 32 * i) * lda;
            float4 v;
            if (kg + 3 < klen) {
                v = STREAM_A ? __ldcs((const float4*)(ap + kg))
                             : *(const float4*)(ap + kg);
            } else {
                v.x = (kg + 0 < klen) ? ap[kg + 0] : 0.0f;
                v.y = (kg + 1 < klen) ? ap[kg + 1] : 0.0f;
                v.z = (kg + 2 < klen) ? ap[kg + 2] : 0.0f;
                v.w = (kg + 3 < klen) ? ap[kg + 3] : 0.0f;
            }
            av[i] = v;
        }
        float4 bv2[2];
        #pragma unroll
        for (int i = 0; i < 2; i++) {
            const int q  = t + 256 * i;
            const int kr = kk + (q >> 4);
            float4 v = make_float4(0.f, 0.f, 0.f, 0.f);
            if (kr < klen) v = *(const float4*)(Wb + (size_t)kr * 64 + (q & 15) * 4);
            bv2[i] = v;
        }

        __syncthreads();
        #pragma unroll
        for (int i = 0; i < 2; i++) {
            As[af4 + 0][arow + 32 * i] = av[i].x;
            As[af4 + 1][arow + 32 * i] = av[i].y;
            As[af4 + 2][arow + 32 * i] = av[i].z;
            As[af4 + 3][arow + 32 * i] = av[i].w;
        }
        *(float4*)(Bs + (size_t)t * 4)         = bv2[0];
        *(float4*)(Bs + (size_t)(t + 256) * 4) = bv2[1];
        __syncthreads();

        #pragma unroll
        for (int k = 0; k < 32; k++) {
            const unsigned long long A0 = *(const unsigned long long*)&As[k][ty * 4];
            const unsigned long long A1 = *(const unsigned long long*)&As[k][ty * 4 + 2];
            const float4 bv = *(const float4*)(Bs + k * 64 + tx * 4);
            const unsigned long long Bq0 = dup2(bv.x);
            const unsigned long long Bq1 = dup2(bv.y);
            const unsigned long long Bq2 = dup2(bv.z);
            const unsigned long long Bq3 = dup2(bv.w);
            ffma2(acc[0][0], A0, Bq0); ffma2(acc[1][0], A1, Bq0);
            ffma2(acc[0][1], A0, Bq1); ffma2(acc[1][1], A1, Bq1);
            ffma2(acc[0][2], A0, Bq2); ffma2(acc[1][2], A1, Bq2);
            ffma2(acc[0][3], A0, Bq3); ffma2(acc[1][3], A1, Bq3);
        }
    }

    float* outp = g_part + ((size_t)c * B_ + row0 + ty * 4) * 64 + tx * 4;
    #pragma unroll
    for (int p = 0; p < 2; p++) {
        const float2 u0 = unpk(acc[p][0]);
        const float2 u1 = unpk(acc[p][1]);
        const float2 u2 = unpk(acc[p][2]);
        const float2 u3 = unpk(acc[p][3]);
        *(float4*)(outp + (size_t)(2 * p) * 64)     = make_float4(u0.x, u1.x, u2.x, u3.x);
        *(float4*)(outp + (size_t)(2 * p + 1) * 64) = make_float4(u0.y, u1.y, u2.y, u3.y);
    }
}

// =============================================================================
// Fused kernel.
//  blocks [0, NZBLK):        14 z-GEMM chunks x 16 row tiles (compute-bound)
//  blocks [NZBLK, NZBLK+250): gene stage. One warp owns gene-group p (4 genes):
//    Wg float4 + bias live in REGISTERS, warp loops over a 256-row b-chunk.
//    Only ONE LDG.128 per warp-item (x only) -> halves L1tex wavefronts vs R3.
// =============================================================================
__global__ void __launch_bounds__(256, 5) fused_kernel(
    const float* __restrict__ x,
    const float* __restrict__ z1, const float* __restrict__ z2,
    const float* __restrict__ z3,
    const float* __restrict__ Wg, const float* __restrict__ bg,
    const float* __restrict__ W1, const float* __restrict__ W2,
    const float* __restrict__ W3)
{
    const int bid = blockIdx.x;
    if (bid < NZBLK) {
        const int zc   = bid >> 4;            // 0..13
        const int row0 = (bid & 15) * 64;
        const float* A; const float* W; int lda, k0;
        if (zc < 8)       { A = z1; W = W1; lda = 4096; k0 = zc * 512; }
        else if (zc < 12) { A = z2; W = W2; lda = 2048; k0 = (zc - 8)  * 512; }
        else              { A = z3; W = W3; lda = 1024; k0 = (zc - 12) * 512; }
        gemm_body<true>(A, W, lda, k0, 512, 10 + zc, row0);
        return;
    }

    // ---- gene population ----
    const int lane = threadIdx.x & 31;
    const int w    = (bid - NZBLK) * 8 + (threadIdx.x >> 5);  // 0..1999
    const int p    = w >> 2;                 // gene group 0..499
    const int b0   = (w & 3) * 256;          // b-chunk

    // register-resident weights & bias for this warp's 4 genes
    const float4 wv  = *(const float4*)(Wg + (size_t)p * 128 + lane * 4);
    const int    g   = p * 4 + (lane >> 3);
    const float  bias = __ldg(bg + g);
    const bool   is_store_lane = (lane & 7) == 0;

    const float* xp = x + (size_t)b0 * ROWSTRIDE + (size_t)p * 128 + lane * 4;
    float* gp = g_gene + (size_t)b0 * G_ + g;

    for (int i = 0; i < 256; i += 8) {
        float4 xv[8];
        #pragma unroll
        for (int j = 0; j < 8; j++)
            xv[j] = __ldcs((const float4*)(xp + (size_t)(i + j) * ROWSTRIDE));

        float d[8];
        #pragma unroll
        for (int j = 0; j < 8; j++)
            d[j] = xv[j].x * wv.x + xv[j].y * wv.y + xv[j].z * wv.z + xv[j].w * wv.w;

        #pragma unroll
        for (int j = 0; j < 8; j++) {
            d[j] += __shfl_down_sync(0xffffffffu, d[j], 4);
            d[j] += __shfl_down_sync(0xffffffffu, d[j], 2);
            d[j] += __shfl_down_sync(0xffffffffu, d[j], 1);
        }
        if (is_store_lane) {
            #pragma unroll
            for (int j = 0; j < 8; j++)
                gp[(size_t)(i + j) * G_] = fmaxf(d[j] + bias, 0.0f);
        }
    }
}

// =============================================================================
// Gene-GEMM kernel: chunks 0..9 (K=200 each), 160 blocks = ~1 full wave.
// =============================================================================
__global__ void __launch_bounds__(256, 5) gene_gemm_kernel(const float* __restrict__ W0)
{
    const int c    = blockIdx.y;                  // 0..9
    const int row0 = blockIdx.x * 64;
    gemm_body<false>(g_gene, W0, G_, c * 200, 200, c, row0);
}

// =============================================================================
// Finish kernel: reduce split-K partials, fusion, final 64->64->64->1 MLP.
// =============================================================================
__global__ void __launch_bounds__(256) finish_kernel(
    const float* __restrict__ b0, const float* __restrict__ b1,
    const float* __restrict__ b2, const float* __restrict__ b3,
    const float* __restrict__ w1, const float* __restrict__ w2,
    const float* __restrict__ w3,
    const float* __restrict__ fW1, const float* __restrict__ fb1,
    const float* __restrict__ fW2, const float* __restrict__ fb2,
    const float* __restrict__ fW3, const float* __restrict__ fb3,
    float* __restrict__ out)
{
    __shared__ float sW1[64 * 64];
    __shared__ float sW2[64 * 64];
    __shared__ float sbuf[4][64];
    __shared__ float sred[8];

    const int t = threadIdx.x;
    const int h = t & 63;
    const int r = t >> 6;
    for (int i = t; i < 64 * 64; i += 256) { sW1[i] = fW1[i]; sW2[i] = fW2[i]; }

    const int b = blockIdx.x * 4 + r;

    float a0 = 0.f, a1 = 0.f, a2 = 0.f, a3 = 0.f;
    #pragma unroll
    for (int cc = 0;  cc < 10; cc++) a0 += g_part[((size_t)cc * B_ + b) * 64 + h];
    #pragma unroll
    for (int cc = 10; cc < 18; cc++) a1 += g_part[((size_t)cc * B_ + b) * 64 + h];
    #pragma unroll
    for (int cc = 18; cc < 22; cc++) a2 += g_part[((size_t)cc * B_ + b) * 64 + h];
    #pragma unroll
    for (int cc = 22; cc < 24; cc++) a3 += g_part[((size_t)cc * B_ + b) * 64 + h];

    float d = fmaxf(a0 + b0[h], 0.f);
    d += fmaxf(a1 + b1[h], 0.f) * w1[h];
    d += fmaxf(a2 + b2[h], 0.f) * w2[h];
    d += fmaxf(a3 + b3[h], 0.f) * w3[h];

    __syncthreads();
    sbuf[r][h] = d;
    __syncthreads();
    float acc = fb1[h];
    #pragma unroll
    for (int k = 0; k < 64; k++) acc = fmaf(sbuf[r][k], sW1[k * 64 + h], acc);
    const float hv = fmaxf(acc, 0.f);
    __syncthreads();
    sbuf[r][h] = hv;
    __syncthreads();
    acc = fb2[h];
    #pragma unroll
    for (int k = 0; k < 64; k++) acc = fmaf(sbuf[r][k], sW2[k * 64 + h], acc);
    const float h2 = fmaxf(acc, 0.f);

    float val = h2 * fW3[h];
    #pragma unroll
    for (int off = 16; off; off >>= 1) val += __shfl_down_sync(0xffffffffu, val, off);
    if ((t & 31) == 0) sred[t >> 5] = val;
    __syncthreads();
    if (h == 0) out[b] = sred[2 * r] + sred[2 * r + 1] + fb3[0];
}

// =============================================================================
// Launcher (graph-capturable: 3 kernel launches, no sync, no alloc)
// =============================================================================
extern "C" void kernel_launch(void* const* d_in, const int* in_sizes, int n_in,
                              void* d_out, int out_size)
{
    const float* x   = (const float*)d_in[0];
    const float* z1  = (const float*)d_in[1];
    const float* z2  = (const float*)d_in[2];
    const float* z3  = (const float*)d_in[3];
    const float* Wg  = (const float*)d_in[4];
    const float* bg  = (const float*)d_in[5];
    const float* W0  = (const float*)d_in[6];
    const float* b0  = (const float*)d_in[7];
    const float* W1  = (const float*)d_in[8];
    const float* b1  = (const float*)d_in[9];
    const float* W2  = (const float*)d_in[10];
    const float* b2  = (const float*)d_in[11];
    const float* W3  = (const float*)d_in[12];
    const float* b3  = (const float*)d_in[13];
    const float* w1  = (const float*)d_in[14];
    const float* w2  = (const float*)d_in[15];
    const float* w3  = (const float*)d_in[16];
    const float* fW1 = (const float*)d_in[17];
    const float* fb1 = (const float*)d_in[18];
    const float* fW2 = (const float*)d_in[19];
    const float* fb2 = (const float*)d_in[20];
    const float* fW3 = (const float*)d_in[21];
    const float* fb3 = (const float*)d_in[22];
    float* out = (float*)d_out;

    fused_kernel<<<NZBLK + GENEBLK, 256>>>(x, z1, z2, z3, Wg, bg, W1, W2, W3);
    gene_gemm_kernel<<<dim3(B_ / 64, 10), 256>>>(W0);
    finish_kernel<<<B_ / 4, 256>>>(b0, b1, b2, b3, w1, w2, w3,
                                   fW1, fb1, fW2, fb2, fW3, fb3, out);
}